// round 4
// baseline (speedup 1.0000x reference)
#include <cuda_runtime.h>
#include <cfloat>

// Caffe-style RoI max pooling matching the XLA-executed JAX reference:
//   x:    [N=2, C=256, H=64, W=64] float32
//   rois: [R=2048, 5] float32  (b, x1, y1, x2, y2), spatial_scale = 1/16
//   out:  [R, C, 7, 7] float32
//
// KEY NUMERIC DETAIL: XLA's algebraic simplifier rewrites division by a
// constant into multiplication by the f32 reciprocal. So the reference's
// bin_w = roi_w / 7.0 is actually roi_w * RN(1/7) (0x3E124925), which for
// roi_w in {21, 42, 49} lands one ulp ABOVE the exact quotient and extends
// every ceil() bin end by one column. We replicate that exactly.

#define PH 7
#define PW 7
#define SCALE 0.0625f
#define NTHR 256

__global__ void __launch_bounds__(NTHR, 8)
roipool_recip_kernel(const float* __restrict__ x,
                     const float* __restrict__ rois,
                     float* __restrict__ out)
{
    const int H = 64, W = 64, C = 256;
    __shared__ int s_ws[PW], s_we[PW], s_hs[PH], s_he[PH];
    __shared__ int s_b;

    const int r = blockIdx.x;
    const float* roi = rois + (size_t)r * 5;

    if (threadIdx.x == 0) {
        // jnp.round == rintf (round half to even); *0.0625 is exact.
        const int xs = (int)rintf(__fmul_rn(roi[1], SCALE));
        const int ys = (int)rintf(__fmul_rn(roi[2], SCALE));
        const int xe = (int)rintf(__fmul_rn(roi[3], SCALE));
        const int ye = (int)rintf(__fmul_rn(roi[4], SCALE));
        const float roi_w = (float)max(xe - xs + 1, 1);
        const float roi_h = (float)max(ye - ys + 1, 1);
        // XLA: divide-by-constant -> multiply-by-RN(1/7)
        const float rc7 = __uint_as_float(0x3E124925u);   // RN(1/7)
        const float bw = __fmul_rn(roi_w, rc7);
        const float bh = __fmul_rn(roi_h, rc7);
        #pragma unroll
        for (int p = 0; p < 7; ++p) {
            const float pf = (float)p;
            s_ws[p] = min(max((int)floorf(__fmul_rn(pf, bw)) + xs, 0), W);
            s_we[p] = min(max((int)ceilf(__fmul_rn(pf + 1.0f, bw)) + xs, 0), W);
            s_hs[p] = min(max((int)floorf(__fmul_rn(pf, bh)) + ys, 0), H);
            s_he[p] = min(max((int)ceilf(__fmul_rn(pf + 1.0f, bh)) + ys, 0), H);
        }
        s_b = (int)roi[0];
    }
    __syncthreads();

    const int plane = H * W;                      // 4096
    const float* feat_base = x + (size_t)s_b * C * plane;
    float* out_r = out + (size_t)r * C * (PH * PW);

    // 12544 outputs, 256 threads -> exactly 49 per thread, coalesced stores.
    #pragma unroll 1
    for (int idx = threadIdx.x; idx < C * PH * PW; idx += NTHR) {
        const int pw = idx % PW;
        const int t  = idx / PW;
        const int ph = t % PH;
        const int c  = t / PH;

        const int ws = s_ws[pw], we = s_we[pw];
        const int hs = s_hs[ph], he = s_he[ph];

        float m = -FLT_MAX;
        const float* f = feat_base + (size_t)c * plane;
        for (int h = hs; h < he; ++h) {
            const float* row = f + h * W;
            #pragma unroll 4
            for (int w = ws; w < we; ++w) {
                m = fmaxf(m, __ldg(row + w));
            }
        }
        out_r[idx] = (he <= hs || we <= ws) ? 0.0f : m;
    }
}

extern "C" void kernel_launch(void* const* d_in, const int* in_sizes, int n_in,
                              void* d_out, int out_size)
{
    const float* x    = (const float*)d_in[0];
    const float* rois = (const float*)d_in[1];
    float* out        = (float*)d_out;
    const int R = in_sizes[1] / 5;

    roipool_recip_kernel<<<R, NTHR>>>(x, rois, out);
}